// round 17
// baseline (speedup 1.0000x reference)
#include <cuda_runtime.h>
#include <cuda_bf16.h>
#include <cstdint>

#define B_   4
#define V_   778
#define F_   1538
#define RW   256
#define NPIX (RW * RW)
#define FARV 10.0f
#define TILE 32
#define NTX  (RW / TILE)        // 8 tiles per axis
#define NTIL (B_ * NTX * NTX)   // 256 tiles
#define SL4  ((F_ + 3) / 4)     // 385 tris per slice
#define NRB  (NTX * NTX * B_ * 2) // raster blocks = 512 (guaranteed resident)
#define HX   0.12109375f        // 32x32 tile half-extent in NDC

// ---------------- scratch (static device globals; no allocation) -------------
__device__ float    g_uvz [B_ * V_ * 3];
__device__ float4   g_e0  [B_ * F_];   // U0,V0,W0,|U0|+|V0|
__device__ float4   g_e1  [B_ * F_];
__device__ float4   g_e2  [B_ * F_];
__device__ float4   g_gi  [B_ * F_];   // Gx,Gy,Gc,-
__device__ float4   g_bbox[B_ * F_];
__device__ unsigned g_Lu  [NTIL];      // per-tile occlusion bound (inv, as uint)
__device__ float4   g_pA  [NTIL * F_]; // packed partial recs
__device__ float4   g_pB  [NTIL * F_];
__device__ float    g_pC  [NTIL * F_];
__device__ float4   g_fl  [NTIL * F_]; // full-accept recs
__device__ int      g_np  [NTIL];
__device__ int      g_nf  [NTIL];
__device__ unsigned g_mx  [B_];
__device__ unsigned g_mn  [B_];
__device__ unsigned g_cnt;

// ---------------- K1: project vertices + clear small scratch -----------------
__global__ void __launch_bounds__(256) k_project(const float* __restrict__ verts,
                                                 const float* __restrict__ intr,
                                                 const float* __restrict__ R,
                                                 const float* __restrict__ t,
                                                 const float* __restrict__ dist) {
    int idx = blockIdx.x * 256 + threadIdx.x;
    if (idx < B_) { g_mx[idx] = 0u; g_mn[idx] = __float_as_uint(FARV); }
    if (idx == 0) g_cnt = 0u;
    if (idx >= B_ * V_) return;
    int b = idx / V_;
    const float* p  = verts + idx * 3;
    const float* Rb = R    + b * 9;
    const float* tb = t    + b * 3;
    const float* Kb = intr + b * 9;
    const float* db = dist + b * 5;

    float px = p[0], py = p[1], pz = p[2];
    float x = Rb[0]*px + Rb[1]*py + Rb[2]*pz + tb[0];
    float y = Rb[3]*px + Rb[4]*py + Rb[5]*pz + tb[1];
    float z = Rb[6]*px + Rb[7]*py + Rb[8]*pz + tb[2];

    float zi = z + 1e-9f;
    float x_ = x / zi, y_ = y / zi;
    float k1 = db[0], k2 = db[1], p1 = db[2], p2 = db[3], k3 = db[4];
    float r2 = x_*x_ + y_*y_;
    float radial = 1.0f + k1*r2 + k2*r2*r2 + k3*r2*r2*r2;
    float x2 = x_*radial + 2.0f*p1*x_*y_ + p2*(r2 + 2.0f*x_*x_);
    float y2 = y_*radial + p1*(r2 + 2.0f*y_*y_) + 2.0f*p2*x_*y_;
    float u  = Kb[0]*x2 + Kb[1]*y2 + Kb[2];
    float vv = Kb[3]*x2 + Kb[4]*y2 + Kb[5];
    vv = 256.0f - vv;
    u  = 2.0f * (u  - 128.0f) / 256.0f;
    vv = 2.0f * (vv - 128.0f) / 256.0f;

    g_uvz[idx*3 + 0] = u;
    g_uvz[idx*3 + 1] = vv;
    g_uvz[idx*3 + 2] = z;
}

// ---------------- K2: triangle setup + clear per-tile counters ---------------
__global__ void __launch_bounds__(256) k_setup(const int* __restrict__ faces) {
    int gid = blockIdx.x * 256 + threadIdx.x;
    if (gid < NTIL) { g_Lu[gid] = 0u; g_np[gid] = 0; g_nf[gid] = 0; }
    if (gid >= B_ * F_) return;
    int b = gid / F_;

    int base = gid * 3;
    int i0 = faces[base + 0], i1 = faces[base + 1], i2 = faces[base + 2];

    const float* va = g_uvz + (b * V_ + i0) * 3;
    const float* vb = g_uvz + (b * V_ + i1) * 3;
    const float* vc = g_uvz + (b * V_ + i2) * 3;
    float ax = va[0], ay = va[1], az = va[2];
    float bx = vb[0], by = vb[1], bz = vb[2];
    float cx = vc[0], cy = vc[1], cz = vc[2];

    float den = (bx - ax) * (cy - ay) - (by - ay) * (cx - ax);
    bool ok = (fabsf(den) > 1e-8f) && (az > 1e-8f) && (bz > 1e-8f) && (cz > 1e-8f);

    float4 e0, e1, e2, gi, bb;
    if (!ok) {
        e0 = make_float4(0.f, 0.f, -1e30f, 0.f);
        e1 = make_float4(0.f, 0.f, 0.f, 0.f);
        e2 = make_float4(0.f, 0.f, 0.f, 0.f);
        gi = make_float4(0.f, 0.f, 0.f, 0.f);
        bb = make_float4(2e30f, -2e30f, 2e30f, -2e30f);
    } else {
        float id = 1.0f / den;
        float U0 = (by - cy) * id, V0 = (cx - bx) * id;
        float W0 = -(U0 * cx + V0 * cy);
        float U1 = (cy - ay) * id, V1 = (ax - cx) * id;
        float W1 = -(U1 * cx + V1 * cy);
        float U2 = -(U0 + U1), V2 = -(V0 + V1), W2 = 1.0f - W0 - W1;
        float ra = 1.0f / az, rb = 1.0f / bz, rc = 1.0f / cz;
        float dA = ra - rc, dB = rb - rc;
        float Gx = U0 * dA + U1 * dB;
        float Gy = V0 * dA + V1 * dB;
        float Gc = rc + W0 * dA + W1 * dB;
        e0 = make_float4(U0, V0, W0, fabsf(U0) + fabsf(V0));
        e1 = make_float4(U1, V1, W1, fabsf(U1) + fabsf(V1));
        e2 = make_float4(U2, V2, W2, fabsf(U2) + fabsf(V2));
        gi = make_float4(Gx, Gy, Gc, 0.f);
        bb = make_float4(fminf(ax, fminf(bx, cx)), fmaxf(ax, fmaxf(bx, cx)),
                         fminf(ay, fminf(by, cy)), fmaxf(ay, fmaxf(by, cy)));
    }
    g_e0[gid] = e0; g_e1[gid] = e1; g_e2[gid] = e2;
    g_gi[gid] = gi; g_bbox[gid] = bb;
}

// ---------------- K3: occlusion bound, 4 slices per tile ---------------------
__global__ void __launch_bounds__(256) k_L() {
    __shared__ float sred[256];
    int bz  = blockIdx.z;
    int b   = bz >> 2;
    int sl  = bz & 3;
    int tid = threadIdx.x;
    int tx  = blockIdx.x * TILE;
    int ty  = blockIdx.y * TILE;
    int til = (b * NTX + blockIdx.y) * NTX + blockIdx.x;
    int t0  = sl * SL4;
    int t1  = min(F_, t0 + SL4);

    float xlo = 2.0f * (tx +  0.5f) / 256.0f - 1.0f;
    float xhi = 2.0f * (tx + 31.5f) / 256.0f - 1.0f;
    float ylo = 2.0f * (ty +  0.5f) / 256.0f - 1.0f;
    float yhi = 2.0f * (ty + 31.5f) / 256.0f - 1.0f;
    float xc  = 0.5f * (xlo + xhi);
    float yc  = 0.5f * (ylo + yhi);

    const float4* e0p  = g_e0   + b * F_;
    const float4* e1p  = g_e1   + b * F_;
    const float4* e2p  = g_e2   + b * F_;
    const float4* gip  = g_gi   + b * F_;
    const float4* bbox = g_bbox + b * F_;

    float L = 0.f;
    for (int tI = t0 + tid; tI < t1; tI += 256) {
        float4 bb = bbox[tI];
        if (bb.x > xlo || bb.y < xhi || bb.z > ylo || bb.w < yhi) continue;
        float4 r0 = e0p[tI];
        float4 r1 = e1p[tI];
        float4 r2 = e2p[tI];
        float cv0 = fmaf(r0.x, xc, fmaf(r0.y, yc, r0.z));
        float cv1 = fmaf(r1.x, xc, fmaf(r1.y, yc, r1.z));
        float cv2 = fmaf(r2.x, xc, fmaf(r2.y, yc, r2.z));
        float E0 = r0.w * HX, E1 = r1.w * HX, E2 = r2.w * HX;
        float me0 = fmaf(E0, 2e-6f, 1e-6f);
        float me1 = fmaf(E1, 2e-6f, 1e-6f);
        float me2 = fmaf(E2, 2e-6f, 1e-6f);
        if ((cv0 - E0 > me0) && (cv1 - E1 > me1) && (cv2 - E2 > me2)) {
            float4 gi = gip[tI];
            float ivc = fmaf(gi.x, xc, fmaf(gi.y, yc, gi.z));
            float Ei  = (fabsf(gi.x) + fabsf(gi.y)) * HX;
            L = fmaxf(L, ivc - Ei);
        }
    }
    sred[tid] = L;
    __syncthreads();
    for (int s = 128; s > 0; s >>= 1) {
        if (tid < s) sred[tid] = fmaxf(sred[tid], sred[tid + s]);
        __syncthreads();
    }
    if (tid == 0 && sred[0] > 0.f)
        atomicMax(&g_Lu[til], __float_as_uint(sred[0]));
}

// ---------------- K4: classification, 4 slices per tile ----------------------
__global__ void __launch_bounds__(256) k_classify() {
    int bz  = blockIdx.z;
    int b   = bz >> 2;
    int sl  = bz & 3;
    int tid = threadIdx.x;
    int tx  = blockIdx.x * TILE;
    int ty  = blockIdx.y * TILE;
    int til = (b * NTX + blockIdx.y) * NTX + blockIdx.x;
    int t0  = sl * SL4;
    int t1  = min(F_, t0 + SL4);

    float xlo = 2.0f * (tx +  0.5f) / 256.0f - 1.0f;
    float xhi = 2.0f * (tx + 31.5f) / 256.0f - 1.0f;
    float ylo = 2.0f * (ty +  0.5f) / 256.0f - 1.0f;
    float yhi = 2.0f * (ty + 31.5f) / 256.0f - 1.0f;
    float xc  = 0.5f * (xlo + xhi);
    float yc  = 0.5f * (ylo + yhi);

    const float4* e0p  = g_e0   + b * F_;
    const float4* e1p  = g_e1   + b * F_;
    const float4* e2p  = g_e2   + b * F_;
    const float4* gip  = g_gi   + b * F_;
    const float4* bbox = g_bbox + b * F_;

    float L = __uint_as_float(g_Lu[til]) - 2e-5f;

    float4* pA = g_pA + til * F_;
    float4* pB = g_pB + til * F_;
    float*  pC = g_pC + til * F_;
    float4* fl = g_fl + til * F_;

    for (int tI = t0 + tid; tI < t1; tI += 256) {
        float4 bb = bbox[tI];
        if (bb.x > xhi || bb.y < xlo || bb.z > yhi || bb.w < ylo) continue;
        float4 r0 = e0p[tI];
        float4 r1 = e1p[tI];
        float4 r2 = e2p[tI];
        float cv0 = fmaf(r0.x, xc, fmaf(r0.y, yc, r0.z));
        float cv1 = fmaf(r1.x, xc, fmaf(r1.y, yc, r1.z));
        float cv2 = fmaf(r2.x, xc, fmaf(r2.y, yc, r2.z));
        float E0 = r0.w * HX, E1 = r1.w * HX, E2 = r2.w * HX;
        float me0 = fmaf(E0, 2e-6f, 1e-6f);
        float me1 = fmaf(E1, 2e-6f, 1e-6f);
        float me2 = fmaf(E2, 2e-6f, 1e-6f);

        bool rej = (cv0 + E0 < -me0) || (cv1 + E1 < -me1) || (cv2 + E2 < -me2);
        if (rej) continue;
        float4 gi = gip[tI];
        float ivc = fmaf(gi.x, xc, fmaf(gi.y, yc, gi.z));
        float Ei  = (fabsf(gi.x) + fabsf(gi.y)) * HX;
        if (ivc + Ei < L) continue;
        bool full = (cv0 - E0 > me0) && (cv1 - E1 > me1) && (cv2 - E2 > me2);
        if (full) {
            fl[atomicAdd(&g_nf[til], 1)] = gi;
        } else {
            int k = atomicAdd(&g_np[til], 1);
            pA[k] = make_float4(r0.x, r0.y, r0.z, r1.x);
            pB[k] = make_float4(r1.y, r1.z, gi.x, gi.y);
            pC[k] = gi.z;
        }
    }
}

// ---------------- K5: raster + fused normalize (512 resident blocks) ---------
// grid (8,8,B_*2): block = 32x16 half-tile, 2 px/thread (rows iy, iy+8).
// __launch_bounds__(256,4) caps regs at 64 -> 4 blocks/SM guaranteed by regs,
// smem (11.3KB*4=45KB) and warps (32<=64): 4*148=592 >= 512, barrier-safe.
__global__ void __launch_bounds__(256, 4) k_raster(float* __restrict__ dep,
                                                   float* __restrict__ mask) {
    __shared__ float4 sA[256], sB[256];
    __shared__ float  sC[256];
    __shared__ float  smx[256], smn[256];
    __shared__ float  sMx, sMn;

    int bz   = blockIdx.z;
    int b    = bz >> 1;
    int half = bz & 1;
    int tid  = threadIdx.x;
    int tx   = blockIdx.x * TILE;
    int ty   = blockIdx.y * TILE;
    int til  = (b * NTX + blockIdx.y) * NTX + blockIdx.x;

    int ix  = tx + (tid & 31);
    int iy0 = ty + half * 16 + (tid >> 5);   // rows [half*16, half*16+8)
    int iy1 = iy0 + 8;

    float x  = 2.0f * (ix  + 0.5f) / 256.0f - 1.0f;
    float y0 = 2.0f * (iy0 + 0.5f) / 256.0f - 1.0f;
    float y1 = 2.0f * (iy1 + 0.5f) / 256.0f - 1.0f;

    const float4* pA = g_pA + til * F_;
    const float4* pB = g_pB + til * F_;
    const float*  pC = g_pC + til * F_;
    const float4* fl = g_fl + til * F_;
    int np = g_np[til], nf = g_nf[til];

    float ma = 0.f, mb = 0.f;

    // ---- partial records, staged through shared ----
    for (int c0 = 0; c0 < np; c0 += 256) {
        int j = c0 + tid;
        __syncthreads();
        if (j < np) { sA[tid] = pA[j]; sB[tid] = pB[j]; sC[tid] = pC[j]; }
        __syncthreads();
        int n = min(256, np - c0);
        for (int k = 0; k < n; k++) {
            float4 a = sA[k];
            float4 c = sB[k];
            float gc = sC[k];
            {
                float w0 = fmaf(a.x, x, fmaf(a.y, y0, a.z));
                float w1 = fmaf(a.w, x, fmaf(c.x, y0, c.y));
                float w2 = (1.0f - w0) - w1;
                float iv = fmaf(c.z, x, fmaf(c.w, y0, gc));
                unsigned s = __float_as_uint(w0) | __float_as_uint(w1) | __float_as_uint(w2);
                ma = fmaxf(ma, __uint_as_float(__float_as_uint(iv) | (s & 0x80000000u)));
            }
            {
                float w0 = fmaf(a.x, x, fmaf(a.y, y1, a.z));
                float w1 = fmaf(a.w, x, fmaf(c.x, y1, c.y));
                float w2 = (1.0f - w0) - w1;
                float iv = fmaf(c.z, x, fmaf(c.w, y1, gc));
                unsigned s = __float_as_uint(w0) | __float_as_uint(w1) | __float_as_uint(w2);
                mb = fmaxf(mb, __uint_as_float(__float_as_uint(iv) | (s & 0x80000000u)));
            }
        }
    }

    // ---- full-accept records, staged through shared ----
    for (int c0 = 0; c0 < nf; c0 += 256) {
        int j = c0 + tid;
        __syncthreads();
        if (j < nf) sA[tid] = fl[j];
        __syncthreads();
        int n = min(256, nf - c0);
        #pragma unroll 2
        for (int k = 0; k < n; k++) {
            float4 f = sA[k];
            ma = fmaxf(ma, fmaf(f.x, x, fmaf(f.y, y0, f.z)));
            mb = fmaxf(mb, fmaf(f.x, x, fmaf(f.y, y1, f.z)));
        }
    }

    // ---- z + mask ----
    bool  ca = ma > 0.f, cb = mb > 0.f;
    float za = ca ? fminf(FARV, 1.0f / ma) : FARV;
    float zb = cb ? fminf(FARV, 1.0f / mb) : FARV;
    int   pa = b * NPIX + iy0 * RW + ix;
    int   pb = b * NPIX + iy1 * RW + ix;
    mask[pa] = ca ? 1.0f : 0.0f;
    mask[pb] = cb ? 1.0f : 0.0f;

    // ---- block min/max reduction ----
    float fa = (ca && za < FARV) ? za : 0.f;
    float fb = (cb && zb < FARV) ? zb : 0.f;
    smx[tid] = fmaxf(fa, fb);
    smn[tid] = fminf(za, zb);
    __syncthreads();
    for (int s = 128; s > 0; s >>= 1) {
        if (tid < s) {
            smx[tid] = fmaxf(smx[tid], smx[tid + s]);
            smn[tid] = fminf(smn[tid], smn[tid + s]);
        }
        __syncthreads();
    }
    if (tid == 0) {
        atomicMax(&g_mx[b], __float_as_uint(smx[0]));
        atomicMin(&g_mn[b], __float_as_uint(smn[0]));
        __threadfence();
        atomicAdd(&g_cnt, 1u);
        while (*((volatile unsigned*)&g_cnt) < (unsigned)NRB) { }
        __threadfence();
        sMx = __uint_as_float(*((volatile unsigned*)&g_mx[b]));
        sMn = __uint_as_float(*((volatile unsigned*)&g_mn[b]));
    }
    __syncthreads();

    // ---- fused normalize, z still in registers ----
    float mx = sMx;
    float rd = 1.0f / (mx - sMn + 1e-4f);
    dep[pa] = fminf(fmaxf((mx - za) * rd, 0.0f), 1.0f);
    dep[pb] = fminf(fmaxf((mx - zb) * rd, 0.0f), 1.0f);
}

// ---------------- launch ------------------------------------------------------
extern "C" void kernel_launch(void* const* d_in, const int* in_sizes, int n_in,
                              void* d_out, int out_size) {
    const float* vertices = (const float*)d_in[0];
    const int*   faces    = (const int*)  d_in[1];
    const float* intr     = (const float*)d_in[2];
    const float* R        = (const float*)d_in[3];
    const float* t        = (const float*)d_in[4];
    const float* dist     = (const float*)d_in[5];

    float* out  = (float*)d_out;
    float* dep  = out;
    float* mask = out + B_ * NPIX;

    dim3 sgrid(NTX, NTX, B_ * 4);
    dim3 rgrid(NTX, NTX, B_ * 2);
    k_project<<<(B_ * V_ + 255) / 256, 256>>>(vertices, intr, R, t, dist);
    k_setup<<<(B_ * F_ + 255) / 256, 256>>>(faces);
    k_L<<<sgrid, 256>>>();
    k_classify<<<sgrid, 256>>>();
    k_raster<<<rgrid, 256>>>(dep, mask);
}